// round 1
// baseline (speedup 1.0000x reference)
#include <cuda_runtime.h>
#include <cstdint>

// Problem constants
#define N_ROWS   32768
#define D_DIM    512
#define C_BOOKS  64
#define K_CODES  16
#define M_OUT    128
#define NODES    15

// Scratch: packed 4-bit codes, 8 uint32 per row (64 codebooks * 4 bits)
__device__ __align__(16) uint32_t g_codes[N_ROWS * 8];

// ---------------------------------------------------------------------------
// Kernel 1: encode. Each block loads 32 rows of I into smem (coalesced),
// then each thread traverses 8 decision trees (codebooks) and packs 8x4-bit
// codes into one uint32.
// ---------------------------------------------------------------------------
#define ENC_ROWS    32
#define ENC_THREADS 256
#define ROW_PAD     516   // 512 + 4 pad to break bank alignment

__global__ __launch_bounds__(ENC_THREADS)
void encode_kernel(const float* __restrict__ I,
                   const float* __restrict__ T,
                   const int*   __restrict__ dims)
{
    extern __shared__ float sm[];
    float* Ir = sm;                              // 32 * 516 floats
    float* Ts = sm + ENC_ROWS * ROW_PAD;         // 960 floats
    int*   ds = (int*)(Ts + 960);                // 256 ints

    const int tid = threadIdx.x;
    const int nb  = blockIdx.x * ENC_ROWS;

    for (int i = tid; i < 960; i += ENC_THREADS) Ts[i] = T[i];
    if (tid < 256) ds[tid] = dims[tid];

    // Coalesced float4 load of 32 full rows of I
    const float4* Ig = (const float4*)(I + (size_t)nb * D_DIM);
    #pragma unroll 4
    for (int q = tid; q < ENC_ROWS * D_DIM / 4; q += ENC_THREADS) {
        float4 v = Ig[q];
        int r = q / (D_DIM / 4);
        int j = (q % (D_DIM / 4)) * 4;
        float* dst = Ir + r * ROW_PAD + j;
        dst[0] = v.x; dst[1] = v.y; dst[2] = v.z; dst[3] = v.w;
    }
    __syncthreads();

    const int r  = tid >> 3;       // row within tile (0..31)
    const int cg = tid & 7;        // codebook group: handles c = cg*8 .. cg*8+7
    const float* row = Ir + r * ROW_PAD;

    uint32_t pack = 0;
    #pragma unroll
    for (int j = 0; j < 8; j++) {
        const int c = cg * 8 + j;
        const int*   dp = ds + c * 4;
        const float* tp = Ts + c * NODES;
        const float v0 = row[dp[0]];
        const float v1 = row[dp[1]];
        const float v2 = row[dp[2]];
        const float v3 = row[dp[3]];
        // Greedy tree traversal == argmax of b (tanh/softmax STE terms cancel)
        int p;
        p = (v0 > tp[0]) ? 1 : 0;                 // level 0: node 0
        p = (p << 1) | ((v1 > tp[1 + p]) ? 1 : 0); // level 1: node 1+p
        p = (p << 1) | ((v2 > tp[3 + p]) ? 1 : 0); // level 2: node 3+p
        p = (p << 1) | ((v3 > tp[7 + p]) ? 1 : 0); // level 3: node 7+p
        pack |= ((uint32_t)p) << (4 * j);
    }
    g_codes[(size_t)(nb + r) * 8 + cg] = pack;    // coalesced store
}

// ---------------------------------------------------------------------------
// Kernel 2: aggregate. out[n, m] = sum_c L[m, c, code[n,c]].
// Block = (ROWTILE rows) x (MTILE=32 m-columns). LUT slice staged in smem as
// lut[c][k][m] with stride 33 -> warp (lane = m) LDS reads are conflict-free
// 128B transactions; code-word reads are smem broadcasts.
// ---------------------------------------------------------------------------
#define AGG_THREADS 512
#define ROWTILE     256
#define MTILE       32
#define LUT_STRIDE  33                      // 32 m + 1 pad
#define LUT_FLOATS  (C_BOOKS * K_CODES * LUT_STRIDE)   // 33792

__global__ __launch_bounds__(AGG_THREADS)
void agg_kernel(const float* __restrict__ L, float* __restrict__ out)
{
    extern __shared__ float sm[];
    float*    lut = sm;                               // 33792 floats (132KB)
    uint32_t* cs  = (uint32_t*)(sm + LUT_FLOATS);     // ROWTILE*8 uint32

    const int tid = threadIdx.x;
    const int n0  = blockIdx.x * ROWTILE;
    const int m0  = blockIdx.y * MTILE;

    // Stage LUT slice: L[(m0+m)*1024 + c*16 + k] -> lut[c*528 + k*33 + m]
    // gmem: coalesced float4. smem: scalar stores, bank stride 33 -> ok.
    const float4* Lg = (const float4*)(L + (size_t)m0 * (C_BOOKS * K_CODES));
    for (int q = tid; q < MTILE * 1024 / 4; q += AGG_THREADS) {
        float4 v = Lg[q];
        int m = q >> 8;            // 256 float4 per L row
        int j = (q & 255) * 4;     // c*16 + k
        int c = j >> 4;
        int k = j & 15;
        float* dst = lut + c * (K_CODES * LUT_STRIDE) + k * LUT_STRIDE + m;
        dst[0]              = v.x;
        dst[LUT_STRIDE]     = v.y;
        dst[2 * LUT_STRIDE] = v.z;
        dst[3 * LUT_STRIDE] = v.w;
    }
    // Stage codes for this row tile (coalesced uint4)
    const uint4* cgm = (const uint4*)(g_codes + (size_t)n0 * 8);
    for (int q = tid; q < ROWTILE * 8 / 4; q += AGG_THREADS) {
        ((uint4*)cs)[q] = cgm[q];
    }
    __syncthreads();

    const int w    = tid >> 5;     // warp 0..15
    const int lane = tid & 31;     // m within tile

    for (int r = w; r < ROWTILE; r += (AGG_THREADS / 32)) {
        const uint32_t* cw = cs + r * 8;
        float a[4] = {0.f, 0.f, 0.f, 0.f};
        #pragma unroll
        for (int q = 0; q < 8; q++) {
            const uint32_t word = cw[q];       // smem broadcast
            #pragma unroll
            for (int j = 0; j < 8; j++) {
                const int k = (word >> (4 * j)) & 15;
                const int c = q * 8 + j;
                a[j & 3] += lut[c * (K_CODES * LUT_STRIDE) + k * LUT_STRIDE + lane];
            }
        }
        out[(size_t)(n0 + r) * M_OUT + m0 + lane] = (a[0] + a[1]) + (a[2] + a[3]);
    }
}

// ---------------------------------------------------------------------------
extern "C" void kernel_launch(void* const* d_in, const int* in_sizes, int n_in,
                              void* d_out, int out_size)
{
    (void)in_sizes; (void)n_in; (void)out_size;
    const float* I    = (const float*)d_in[0];
    const float* T    = (const float*)d_in[1];
    const float* L    = (const float*)d_in[2];
    // d_in[3] = S, d_in[4] = B (structure baked into the kernels)
    const int*   dims = (const int*)d_in[5];
    // d_in[6] = temp (>0, does not affect the forward value)
    float* out = (float*)d_out;

    const int encSmem = (ENC_ROWS * ROW_PAD + 960 + 256) * 4;          // ~70.9 KB
    const int aggSmem = (LUT_FLOATS + ROWTILE * 8) * 4;                // ~140 KB
    cudaFuncSetAttribute(encode_kernel, cudaFuncAttributeMaxDynamicSharedMemorySize, encSmem);
    cudaFuncSetAttribute(agg_kernel,    cudaFuncAttributeMaxDynamicSharedMemorySize, aggSmem);

    encode_kernel<<<N_ROWS / ENC_ROWS, ENC_THREADS, encSmem>>>(I, T, dims);
    agg_kernel<<<dim3(N_ROWS / ROWTILE, M_OUT / MTILE), AGG_THREADS, aggSmem>>>(L, out);
}

// round 2
// speedup vs baseline: 1.3017x; 1.3017x over previous
#include <cuda_runtime.h>
#include <cstdint>

// Problem constants
#define N_ROWS   32768
#define D_DIM    512
#define C_BOOKS  64
#define K_CODES  16
#define M_OUT    128
#define NODES    15

// Scratch: packed 4-bit codes, 8 uint32 per row (64 codebooks * 4 bits)
__device__ __align__(16) uint32_t g_codes[N_ROWS * 8];

// ---------------------------------------------------------------------------
// Kernel 1: encode (unchanged structure). Each block loads 32 rows of I into
// smem coalesced, then each thread traverses 8 depth-4 trees and packs codes.
// ---------------------------------------------------------------------------
#define ENC_ROWS    32
#define ENC_THREADS 256
#define ROW_PAD     516

__global__ __launch_bounds__(ENC_THREADS)
void encode_kernel(const float* __restrict__ I,
                   const float* __restrict__ T,
                   const int*   __restrict__ dims)
{
    extern __shared__ float sm[];
    float* Ir = sm;
    float* Ts = sm + ENC_ROWS * ROW_PAD;
    int*   ds = (int*)(Ts + 960);

    const int tid = threadIdx.x;
    const int nb  = blockIdx.x * ENC_ROWS;

    for (int i = tid; i < 960; i += ENC_THREADS) Ts[i] = T[i];
    if (tid < 256) ds[tid] = dims[tid];

    const float4* Ig = (const float4*)(I + (size_t)nb * D_DIM);
    #pragma unroll 8
    for (int q = tid; q < ENC_ROWS * D_DIM / 4; q += ENC_THREADS) {
        float4 v = Ig[q];
        int r = q / (D_DIM / 4);
        int j = (q % (D_DIM / 4)) * 4;
        float* dst = Ir + r * ROW_PAD + j;
        dst[0] = v.x; dst[1] = v.y; dst[2] = v.z; dst[3] = v.w;
    }
    __syncthreads();

    const int r  = tid >> 3;
    const int cg = tid & 7;
    const float* row = Ir + r * ROW_PAD;

    uint32_t pack = 0;
    #pragma unroll
    for (int j = 0; j < 8; j++) {
        const int c = cg * 8 + j;
        const int*   dp = ds + c * 4;
        const float* tp = Ts + c * NODES;
        const float v0 = row[dp[0]];
        const float v1 = row[dp[1]];
        const float v2 = row[dp[2]];
        const float v3 = row[dp[3]];
        int p;
        p = (v0 > tp[0]) ? 1 : 0;
        p = (p << 1) | ((v1 > tp[1 + p]) ? 1 : 0);
        p = (p << 1) | ((v2 > tp[3 + p]) ? 1 : 0);
        p = (p << 1) | ((v3 > tp[7 + p]) ? 1 : 0);
        pack |= ((uint32_t)p) << (4 * j);
    }
    g_codes[(size_t)(nb + r) * 8 + cg] = pack;
}

// ---------------------------------------------------------------------------
// Kernel 2: aggregate, float2-vectorized.
// out[n, m] = sum_c L[m, c, code[n,c]].
// LUT in smem as float2 [c][k][m/2]: k-stride 17 float2 (pad), c-stride 273.
// Warp = 2 rows x 16 lanes; each lane accumulates an m-pair via LDS.64.
// ---------------------------------------------------------------------------
#define AGG_THREADS 1024
#define ROWTILE     256
#define MTILE       32
#define K_STRIDE_F2 17                          // 16 data + 1 pad (float2 units)
#define C_STRIDE_F2 (K_CODES * K_STRIDE_F2 + 1) // 273
#define LUT_F2      (C_BOOKS * C_STRIDE_F2)     // 17472 float2 = 139776 B
#define K_STRIDE_B  (K_STRIDE_F2 * 8)           // 136
#define C_STRIDE_B  (C_STRIDE_F2 * 8)           // 2184

__global__ __launch_bounds__(AGG_THREADS)
void agg_kernel(const float* __restrict__ L, float* __restrict__ out)
{
    extern __shared__ float sm[];
    uint32_t* cs = (uint32_t*)(sm + LUT_F2 * 2);   // ROWTILE*8 words, 16B aligned

    const int tid = threadIdx.x;
    const int n0  = blockIdx.x * ROWTILE;
    const int m0  = blockIdx.y * MTILE;

    // Stage LUT slice: L[(m0+m)*1024 + c*16 + k] -> float idx c*546 + k*34 + m
    const float4* Lg = (const float4*)(L + (size_t)m0 * (C_BOOKS * K_CODES));
    for (int q = tid; q < MTILE * 1024 / 4; q += AGG_THREADS) {
        float4 v = Lg[q];
        int m = q >> 8;
        int j = (q & 255) * 4;          // c*16 + k  (k multiple of 4)
        int c = j >> 4;
        int k = j & 15;
        float* dst = sm + c * (C_STRIDE_F2 * 2) + k * (K_STRIDE_F2 * 2) + m;
        dst[0]                    = v.x;
        dst[K_STRIDE_F2 * 2]      = v.y;
        dst[K_STRIDE_F2 * 4]      = v.z;
        dst[K_STRIDE_F2 * 6]      = v.w;
    }
    // Stage codes (coalesced uint4)
    const uint4* cgm = (const uint4*)(g_codes + (size_t)n0 * 8);
    for (int q = tid; q < ROWTILE * 8 / 4; q += AGG_THREADS) {
        ((uint4*)cs)[q] = cgm[q];
    }
    __syncthreads();

    const int wid  = tid >> 5;          // 0..31
    const int lane = tid & 31;
    const int l15  = lane & 15;         // m-pair index
    const int rsel = lane >> 4;         // which row of the pair
    const uint32_t lane_b = (uint32_t)l15 * 8;   // byte offset within k block

    const char* lutb = (const char*)sm;

    #pragma unroll
    for (int it = 0; it < ROWTILE / 64; ++it) {
        const int row = it * 64 + wid * 2 + rsel;   // row within tile
        const uint4* cw = (const uint4*)(cs + row * 8);
        const uint4 w0 = cw[0];
        const uint4 w1 = cw[1];
        const uint32_t words[8] = {w0.x, w0.y, w0.z, w0.w, w1.x, w1.y, w1.z, w1.w};

        float2 acc0 = {0.f, 0.f}, acc1 = {0.f, 0.f};
        float2 acc2 = {0.f, 0.f}, acc3 = {0.f, 0.f};

        #pragma unroll
        for (int q = 0; q < 8; q++) {
            const uint32_t word = words[q];
            #pragma unroll
            for (int j = 0; j < 8; j++) {
                const uint32_t k = (word >> (4 * j)) & 15u;
                const float2 v = *(const float2*)(lutb
                        + (q * 8 + j) * C_STRIDE_B       // compile-time imm
                        + k * K_STRIDE_B + lane_b);
                switch (j & 3) {
                    case 0: acc0.x += v.x; acc0.y += v.y; break;
                    case 1: acc1.x += v.x; acc1.y += v.y; break;
                    case 2: acc2.x += v.x; acc2.y += v.y; break;
                    default: acc3.x += v.x; acc3.y += v.y; break;
                }
            }
        }
        float2 r01 = {acc0.x + acc1.x, acc0.y + acc1.y};
        float2 r23 = {acc2.x + acc3.x, acc2.y + acc3.y};
        float2 res = {r01.x + r23.x, r01.y + r23.y};
        float2* og = (float2*)(out + (size_t)(n0 + row) * M_OUT + m0);
        og[l15] = res;
    }
}

// ---------------------------------------------------------------------------
extern "C" void kernel_launch(void* const* d_in, const int* in_sizes, int n_in,
                              void* d_out, int out_size)
{
    (void)in_sizes; (void)n_in; (void)out_size;
    const float* I    = (const float*)d_in[0];
    const float* T    = (const float*)d_in[1];
    const float* L    = (const float*)d_in[2];
    const int*   dims = (const int*)d_in[5];
    float* out = (float*)d_out;

    const int encSmem = (ENC_ROWS * ROW_PAD + 960 + 256) * 4;
    const int aggSmem = LUT_F2 * 8 + ROWTILE * 8 * 4;        // 139776 + 8192
    cudaFuncSetAttribute(encode_kernel, cudaFuncAttributeMaxDynamicSharedMemorySize, encSmem);
    cudaFuncSetAttribute(agg_kernel,    cudaFuncAttributeMaxDynamicSharedMemorySize, aggSmem);

    encode_kernel<<<N_ROWS / ENC_ROWS, ENC_THREADS, encSmem>>>(I, T, dims);
    agg_kernel<<<dim3(N_ROWS / ROWTILE, M_OUT / MTILE), AGG_THREADS, aggSmem>>>(L, out);
}

// round 4
// speedup vs baseline: 1.9731x; 1.5158x over previous
#include <cuda_runtime.h>
#include <cuda_fp16.h>
#include <cstdint>

// Problem constants
#define N_ROWS   32768
#define D_DIM    512
#define C_BOOKS  64
#define K_CODES  16
#define M_OUT    128
#define NODES    15

// Scratch
__device__ __align__(16) uint32_t g_codes[N_ROWS * 8];               // 4-bit codes
__device__ __align__(16) __half   g_Lf16[M_OUT * C_BOOKS * K_CODES]; // L as fp16 [m][1024]

// ---------------------------------------------------------------------------
// PTX helpers (sm_103 baseline only — no tcgen05, harness targets sm_103)
// ---------------------------------------------------------------------------
__device__ __forceinline__ uint32_t smem_u32(const void* p) {
    uint32_t a;
    asm("{ .reg .u64 t; cvta.to.shared.u64 t, %1; cvt.u32.u64 %0, t; }" : "=r"(a) : "l"(p));
    return a;
}
__device__ __forceinline__ void cp16(uint32_t dst, const void* src) {
    asm volatile("cp.async.cg.shared.global [%0], [%1], 16;" :: "r"(dst), "l"(src) : "memory");
}
#define CP_COMMIT() asm volatile("cp.async.commit_group;" ::: "memory")
#define CP_WAIT(n)  asm volatile("cp.async.wait_group %0;" :: "n"(n) : "memory")

__device__ __forceinline__ void ldsm4(uint32_t& r0, uint32_t& r1, uint32_t& r2,
                                      uint32_t& r3, uint32_t addr) {
    asm volatile("ldmatrix.sync.aligned.m8n8.x4.shared.b16 {%0,%1,%2,%3}, [%4];"
                 : "=r"(r0), "=r"(r1), "=r"(r2), "=r"(r3) : "r"(addr));
}
__device__ __forceinline__ void mma16816(float* c, uint32_t a0, uint32_t a1,
                                         uint32_t a2, uint32_t a3,
                                         uint32_t b0, uint32_t b1) {
    asm volatile("mma.sync.aligned.m16n8k16.row.col.f32.f16.f16.f32 "
                 "{%0,%1,%2,%3}, {%4,%5,%6,%7}, {%8,%9}, {%0,%1,%2,%3};"
                 : "+f"(c[0]), "+f"(c[1]), "+f"(c[2]), "+f"(c[3])
                 : "r"(a0), "r"(a1), "r"(a2), "r"(a3), "r"(b0), "r"(b1));
}

// ---------------------------------------------------------------------------
// Kernel 1: encode. 16 rows/CTA, 256 threads, cp.async row staging.
// Thread = (row, 4 codebooks); greedy tree == argmax (STE terms cancel).
// ---------------------------------------------------------------------------
#define ENC_ROWS    16
#define ENC_THREADS 256
#define ROW_PAD     516

__global__ __launch_bounds__(ENC_THREADS)
void encode_kernel(const float* __restrict__ I,
                   const float* __restrict__ T,
                   const int*   __restrict__ dims)
{
    extern __shared__ float sm[];
    float* Ir = sm;                              // 16 * 516 floats
    float* Ts = sm + ENC_ROWS * ROW_PAD;         // 960
    int*   ds = (int*)(Ts + 960);                // 256

    const int tid = threadIdx.x;
    const int nb  = blockIdx.x * ENC_ROWS;
    const uint32_t sbase = smem_u32(sm);

    for (int i = tid; i < 960; i += ENC_THREADS) Ts[i] = T[i];
    ds[tid] = dims[tid];

    // cp.async staging of 16 rows (2048 x 16B)
    const char* src = (const char*)(I + (size_t)nb * D_DIM);
    #pragma unroll
    for (int i = 0; i < 8; i++) {
        int q = tid + ENC_THREADS * i;
        int r = q >> 7;              // 128 x 16B per row
        int j = q & 127;
        cp16(sbase + (uint32_t)(r * (ROW_PAD * 4) + j * 16),
             src + (size_t)r * (D_DIM * 4) + j * 16);
    }
    CP_COMMIT();
    CP_WAIT(0);
    __syncthreads();

    const int r  = tid >> 4;        // row 0..15
    const int cg = tid & 15;        // 4 codebooks: c = cg*4 + j
    const float* row = Ir + r * ROW_PAD;

    uint32_t pack = 0;
    #pragma unroll
    for (int j = 0; j < 4; j++) {
        const int c = cg * 4 + j;
        const int*   dp = ds + c * 4;
        const float* tp = Ts + c * NODES;
        const float v0 = row[dp[0]];
        const float v1 = row[dp[1]];
        const float v2 = row[dp[2]];
        const float v3 = row[dp[3]];
        int p;
        p = (v0 > tp[0]) ? 1 : 0;
        p = (p << 1) | ((v1 > tp[1 + p]) ? 1 : 0);
        p = (p << 1) | ((v2 > tp[3 + p]) ? 1 : 0);
        p = (p << 1) | ((v3 > tp[7 + p]) ? 1 : 0);
        pack |= ((uint32_t)p) << (4 * j);
    }
    ((uint16_t*)g_codes)[(size_t)(nb + r) * 16 + cg] = (uint16_t)pack;
}

// ---------------------------------------------------------------------------
// Kernel 1.5: L (fp32) -> g_Lf16
// ---------------------------------------------------------------------------
__global__ __launch_bounds__(256)
void convert_kernel(const float* __restrict__ L)
{
    int q = blockIdx.x * 256 + threadIdx.x;     // float4 index, 32768 total
    float4 v = ((const float4*)L)[q];
    ((__half2*)g_Lf16)[q * 2]     = __floats2half2_rn(v.x, v.y);
    ((__half2*)g_Lf16)[q * 2 + 1] = __floats2half2_rn(v.z, v.w);
}

// ---------------------------------------------------------------------------
// Kernel 2: tensor aggregation via mma.sync m16n8k16 (HMMA).
// out = E @ L^T ; E one-hot built IN REGISTERS from codes (no memory).
// CTA: 128 rows x 128 m, 4 warps, warp = 32 rows (2 m16 row-tiles).
// B (L fp16) staged in smem chunks of 128 k x 128 m, double-buffered cp.async.
// Row stride 272B (17x16B) -> conflict-free ldmatrix.
// K-block of 16 == one codebook: code word index per chunk == chunk id.
// ---------------------------------------------------------------------------
#define AGG_THREADS 128
#define NTILE       128
#define BROW        272                         // bytes per m-row in B tile
#define BTILE_B     (128 * BROW)                // 34816
#define SM_B0       4096
#define SM_B1       (4096 + BTILE_B)
#define SM_AGG      (4096 + 2 * BTILE_B)        // 73728

__global__ __launch_bounds__(AGG_THREADS, 2)
void agg_kernel(float* __restrict__ out)
{
    extern __shared__ __align__(16) char smem[];
    const uint32_t sb = smem_u32(smem);
    const int tid  = threadIdx.x;
    const int wid  = tid >> 5;
    const int lane = tid & 31;
    const int g    = lane >> 2;     // 0..7
    const int tg   = lane & 3;      // 0..3
    const int n0   = blockIdx.x * NTILE;

    // Stage codes: 128 rows * 32B = 256 uint4
    {
        const uint4* src = (const uint4*)(g_codes + (size_t)n0 * 8);
        uint4* dst = (uint4*)smem;
        dst[tid]       = src[tid];
        dst[tid + 128] = src[tid + 128];
    }

    // ldmatrix per-lane constant offset: t = lane>>3 selects (nb_off, khalf)
    const int t = lane >> 3;
    const uint32_t lane_m   = (uint32_t)(((t >> 1) * 8) + (lane & 7));
    const uint32_t lane_off = lane_m * BROW + (uint32_t)((t & 1) * 16);

    // Prologue: stage chunk 0 into B0
    {
        const char* srcL = (const char*)g_Lf16;
        #pragma unroll
        for (int i = 0; i < 16; i++) {
            int q = tid + AGG_THREADS * i;
            int m = q >> 4, seg = q & 15;
            cp16(sb + SM_B0 + (uint32_t)(m * BROW + seg * 16),
                 srcL + (size_t)m * 2048 + seg * 16);
        }
        CP_COMMIT();
    }

    float acc[2][16][4];
    #pragma unroll
    for (int rt = 0; rt < 2; rt++)
        #pragma unroll
        for (int nb = 0; nb < 16; nb++)
            #pragma unroll
            for (int i = 0; i < 4; i++) acc[rt][nb][i] = 0.f;

    const uint32_t* cs = (const uint32_t*)smem;
    const int rA = wid * 32 + g;    // row-tile0 row (lane-local)

    #pragma unroll 1
    for (int ch = 0; ch < 8; ch++) {
        // stage next chunk into the other buffer
        if (ch < 7) {
            const char* srcL = (const char*)g_Lf16 + (ch + 1) * 256;
            const uint32_t bnext = sb + ((ch & 1) ? SM_B0 : SM_B1);
            #pragma unroll
            for (int i = 0; i < 16; i++) {
                int q = tid + AGG_THREADS * i;
                int m = q >> 4, seg = q & 15;
                cp16(bnext + (uint32_t)(m * BROW + seg * 16),
                     srcL + (size_t)m * 2048 + seg * 16);
            }
            CP_COMMIT();
            CP_WAIT(1);
        } else {
            CP_WAIT(0);
        }
        __syncthreads();

        const uint32_t bbase = sb + ((ch & 1) ? SM_B1 : SM_B0) + lane_off;

        // code words for this chunk (word index == ch)
        const uint32_t w0 = cs[(rA)      * 8 + ch];
        const uint32_t w1 = cs[(rA + 8)  * 8 + ch];
        const uint32_t w2 = cs[(rA + 16) * 8 + ch];
        const uint32_t w3 = cs[(rA + 24) * 8 + ch];

        #pragma unroll
        for (int kbl = 0; kbl < 8; kbl++) {
            const uint32_t k0 = (w0 >> (4 * kbl)) & 15u;
            const uint32_t k1 = (w1 >> (4 * kbl)) & 15u;
            const uint32_t k2 = (w2 >> (4 * kbl)) & 15u;
            const uint32_t k3 = (w3 >> (4 * kbl)) & 15u;
            // one-hot A fragments (a0a1: row g klo | a2a3: row g+8 klo |
            //                      a4a5: row g khi | a6a7: row g+8 khi)
            const uint32_t hv0 = 0x3C00u << ((k0 & 1u) << 4);
            const uint32_t hv1 = 0x3C00u << ((k1 & 1u) << 4);
            const uint32_t hv2 = 0x3C00u << ((k2 & 1u) << 4);
            const uint32_t hv3 = 0x3C00u << ((k3 & 1u) << 4);
            const uint32_t s0 = k0 >> 1, s1 = k1 >> 1, s2 = k2 >> 1, s3 = k3 >> 1;
            const uint32_t A0 = (s0 == (uint32_t)tg)     ? hv0 : 0u;
            const uint32_t A1 = (s1 == (uint32_t)tg)     ? hv1 : 0u;
            const uint32_t A2 = (s0 == (uint32_t)tg + 4) ? hv0 : 0u;
            const uint32_t A3 = (s1 == (uint32_t)tg + 4) ? hv1 : 0u;
            const uint32_t B0 = (s2 == (uint32_t)tg)     ? hv2 : 0u;
            const uint32_t B1 = (s3 == (uint32_t)tg)     ? hv3 : 0u;
            const uint32_t B2 = (s2 == (uint32_t)tg + 4) ? hv2 : 0u;
            const uint32_t B3 = (s3 == (uint32_t)tg + 4) ? hv3 : 0u;

            const uint32_t bk = bbase + (uint32_t)(kbl * 32);
            #pragma unroll
            for (int p = 0; p < 8; p++) {
                uint32_t b0, b1, b2, b3;
                ldsm4(b0, b1, b2, b3, bk + (uint32_t)(p * 16 * BROW));
                mma16816(acc[0][2 * p],     A0, A1, A2, A3, b0, b1);
                mma16816(acc[0][2 * p + 1], A0, A1, A2, A3, b2, b3);
                mma16816(acc[1][2 * p],     B0, B1, B2, B3, b0, b1);
                mma16816(acc[1][2 * p + 1], B0, B1, B2, B3, b2, b3);
            }
        }
        __syncthreads();
    }

    // Epilogue: direct STG.64 (32B-sector aligned pairs)
    #pragma unroll
    for (int rt = 0; rt < 2; rt++) {
        const int rowA = n0 + wid * 32 + rt * 16 + g;
        #pragma unroll
        for (int nb = 0; nb < 16; nb++) {
            float2 lo = make_float2(acc[rt][nb][0], acc[rt][nb][1]);
            float2 hi = make_float2(acc[rt][nb][2], acc[rt][nb][3]);
            *(float2*)(out + (size_t)rowA * M_OUT + nb * 8 + tg * 2)       = lo;
            *(float2*)(out + (size_t)(rowA + 8) * M_OUT + nb * 8 + tg * 2) = hi;
        }
    }
}

// ---------------------------------------------------------------------------
extern "C" void kernel_launch(void* const* d_in, const int* in_sizes, int n_in,
                              void* d_out, int out_size)
{
    (void)in_sizes; (void)n_in; (void)out_size;
    const float* I    = (const float*)d_in[0];
    const float* T    = (const float*)d_in[1];
    const float* L    = (const float*)d_in[2];
    const int*   dims = (const int*)d_in[5];
    float* out = (float*)d_out;

    const int encSmem = (ENC_ROWS * ROW_PAD + 960 + 256) * 4;  // 37888
    cudaFuncSetAttribute(encode_kernel, cudaFuncAttributeMaxDynamicSharedMemorySize, encSmem);
    cudaFuncSetAttribute(agg_kernel,    cudaFuncAttributeMaxDynamicSharedMemorySize, SM_AGG);

    convert_kernel<<<(M_OUT * C_BOOKS * K_CODES) / (4 * 256), 256>>>(L);
    encode_kernel<<<N_ROWS / ENC_ROWS, ENC_THREADS, encSmem>>>(I, T, dims);
    agg_kernel<<<N_ROWS / NTILE, AGG_THREADS, SM_AGG>>>(out);
}